// round 11
// baseline (speedup 1.0000x reference)
#include <cuda_runtime.h>
#include <cuda_fp16.h>
#include <cstdint>
#include <math.h>

#define BB 16
#define CC 512
#define SS 1024
#define PER_B (CC*SS)

typedef __half f16;

// ---------------- scratch (__device__ globals; no allocs) ----------------
__device__ float g_psum[BB*64], g_psq[BB*64], g_stats[BB*2];
__device__ unsigned g_ctr;
__device__ f16  g_h2 [(size_t)BB*SS*512];    // norm'd [B*S, C] fp16 (A-side)
__device__ f16  g_w1 [1536*512];             // qkv_w fp16 (B-side)
__device__ f16  g_w2 [512*512];              // proj_w fp16 (A-side for proj)
__device__ f16  g_q2 [(size_t)BB*SS*512];    // Q fp16 (A-side)
__device__ f16  g_k2 [(size_t)BB*SS*512];    // K fp16 (B-side)
__device__ f16  g_v2 [(size_t)BB*CC*1024];   // V transposed [B,C,S] fp16 (B-side)
__device__ f16  g_p2 [(size_t)BB*SS*1024];   // probs [B*S, S] fp16 (A-side)
__device__ f16  g_ao2[(size_t)BB*SS*512];    // attn out fp16 (B-side for proj)
__device__ float g_sc [(size_t)BB*SS*SS];    // scores fp32

// ---------------- helpers ----------------
__device__ __forceinline__ uint32_t smem_u32(const void* p) {
    uint32_t a;
    asm("{ .reg .u64 t; cvta.to.shared.u64 t, %1; cvt.u32.u64 %0, t; }" : "=r"(a) : "l"(p));
    return a;
}
#define CP_ASYNC16(dst, src) \
    asm volatile("cp.async.cg.shared.global [%0], [%1], 16;" :: "r"(dst), "l"(src) : "memory")
#define CP_COMMIT() asm volatile("cp.async.commit_group;" ::: "memory")
#define CP_WAIT0()  asm volatile("cp.async.wait_group 0;" ::: "memory")
#define CP_WAIT1()  asm volatile("cp.async.wait_group 1;" ::: "memory")
#define LDM_X4(r0,r1,r2,r3,addr) \
    asm volatile("ldmatrix.sync.aligned.m8n8.x4.shared.b16 {%0,%1,%2,%3}, [%4];" \
        : "=r"(r0),"=r"(r1),"=r"(r2),"=r"(r3) : "r"(addr))
#define MMA16816(d, a, b0, b1) \
    asm volatile("mma.sync.aligned.m16n8k16.row.col.f32.f16.f16.f32 " \
        "{%0,%1,%2,%3}, {%4,%5,%6,%7}, {%8,%9}, {%0,%1,%2,%3};" \
        : "+f"((d)[0]), "+f"((d)[1]), "+f"((d)[2]), "+f"((d)[3]) \
        : "r"((a)[0]), "r"((a)[1]), "r"((a)[2]), "r"((a)[3]), "r"(b0), "r"(b1))

// ---------------- weight convert (plain fp16) ----------------
__global__ void wconv(const float* __restrict__ w1s, const float* __restrict__ w2s) {
    int i = blockIdx.x * 256 + threadIdx.x;
    if (i < 2048*512) {
        if (i < 1536*512) g_w1[i] = __float2half_rn(w1s[i]);
        else              g_w2[i - 1536*512] = __float2half_rn(w2s[i - 1536*512]);
    }
}

// ---------------- fused GroupNorm stats (partial + last-block finalize) ----------------
__global__ void gn_stats(const float* __restrict__ x) {
    int b = blockIdx.y, chunk = blockIdx.x, t = threadIdx.x;
    const float* p = x + (size_t)b*PER_B + (size_t)chunk*8192;
    float s = 0.f, q = 0.f;
#pragma unroll
    for (int i = 0; i < 32; i++) { float v = p[t + i*256]; s += v; q += v*v; }
    __shared__ float ss_[8], sq_[8];
    for (int o = 16; o > 0; o >>= 1) {
        s += __shfl_down_sync(0xffffffffu, s, o);
        q += __shfl_down_sync(0xffffffffu, q, o);
    }
    if ((t & 31) == 0) { ss_[t >> 5] = s; sq_[t >> 5] = q; }
    __syncthreads();
    __shared__ int isLast;
    if (t == 0) {
        float S2 = 0.f, Q2 = 0.f;
#pragma unroll
        for (int i = 0; i < 8; i++) { S2 += ss_[i]; Q2 += sq_[i]; }
        g_psum[b*64 + chunk] = S2; g_psq[b*64 + chunk] = Q2;
        __threadfence();
        unsigned v = atomicAdd(&g_ctr, 1u);
        isLast = (v == 64u*BB - 1u);
    }
    __syncthreads();
    if (isLast) {
        if (t < BB) {
            float s2 = 0.f, q2 = 0.f;
            for (int i = 0; i < 64; i++) { s2 += g_psum[t*64+i]; q2 += g_psq[t*64+i]; }
            float mean = s2 * (1.f/(float)PER_B);
            float var  = q2 * (1.f/(float)PER_B) - mean*mean;
            g_stats[2*t] = mean; g_stats[2*t+1] = rsqrtf(var + 1e-5f);
        }
        if (t == 0) g_ctr = 0u;
    }
}

// ---------------- normalize + transpose -> g_h2 [B*S, C] fp16 ----------------
__global__ void norm_split(const float* __restrict__ x,
                           const float* __restrict__ gw,
                           const float* __restrict__ gb) {
    __shared__ float tile[32][33];
    int b = blockIdx.z;
    int s0 = blockIdx.x * 32, c0 = blockIdx.y * 32;
    int tx = threadIdx.x, ty = threadIdx.y;
    const float* xp = x + (size_t)b * PER_B;
#pragma unroll
    for (int i = 0; i < 4; i++) {
        int c = c0 + ty + i*8;
        tile[ty + i*8][tx] = xp[(size_t)c*SS + s0 + tx];
    }
    __syncthreads();
    float mean = g_stats[2*b], inv = g_stats[2*b+1];
    int c = c0 + tx;
    float w  = gw[c] * inv;
    float bias = gb[c] - mean * w;
#pragma unroll
    for (int i = 0; i < 4; i++) {
        int s = s0 + ty + i*8;
        float v = tile[tx][ty + i*8] * w + bias;
        g_h2[((size_t)b*SS + s) * 512 + c] = __float2half_rn(v);
    }
}

// ---------------- HMMA GEMM: 64x128 CTA, 4 warps (32x64 each), BK=32, 3-stage, occ 4 ----------------
// NT: out[m,n] = sum_k A[m,k]*B[n,k]
// EPI: 0 = QKV out (Q/K direct, V staged transpose), 1 = scores*scale,
//      2 = AV out, 3 = proj^T: A=w2, out[c,s] direct with bias+resid
#define STAGE_BYTES 15360        // A 64x80 (5120) + B 128x80 (10240)
#define DYN_SMEM 46080           // 3 stages; V-staging (64*132*4=33792) fits

__device__ __forceinline__ void prefetch_tile(char* smem, int stage,
    const f16* __restrict__ A, int lda, const f16* __restrict__ B, int ldb,
    int m0, int n0, int k0, int tid)
{
    char* as = smem + stage*STAGE_BYTES;
    char* bs = as + 5120;
    int row = tid >> 1, seg = tid & 1;
    const f16* ag = A + (size_t)(m0 + row)*lda + k0 + seg*16;
    uint32_t asw = smem_u32(as + row*80 + seg*32);
    CP_ASYNC16(asw,      (const void*)ag);
    CP_ASYNC16(asw + 16, (const void*)(ag + 8));
#pragma unroll
    for (int h = 0; h < 2; h++) {
        int brow = row + h*64;
        const f16* bg = B + (size_t)(n0 + brow)*ldb + k0 + seg*16;
        uint32_t bsw = smem_u32(bs + brow*80 + seg*32);
        CP_ASYNC16(bsw,      (const void*)bg);
        CP_ASYNC16(bsw + 16, (const void*)(bg + 8));
    }
}

template<int EPI>
__global__ __launch_bounds__(128, 4)
void mm_gemm(const f16* __restrict__ A, int lda, long long sA,
             const f16* __restrict__ B, int ldb, long long sB,
             float* __restrict__ Out,
             const float* __restrict__ bias,
             const float* __restrict__ resid,
             float scale, int K)
{
    extern __shared__ char smem[];
    int tid = threadIdx.x, lane = tid & 31, wid = tid >> 5;
    int wm = wid >> 1, wn = wid & 1;          // 2 x 2 warp grid, 32x64 tiles
    int z = blockIdx.z;
    int m0 = blockIdx.y * 64, n0 = blockIdx.x * 128;
    A += (size_t)z * sA;
    B += (size_t)z * sB;

    float acc[2][8][4];
#pragma unroll
    for (int i = 0; i < 2; i++)
#pragma unroll
        for (int j = 0; j < 8; j++)
#pragma unroll
            for (int r = 0; r < 4; r++) acc[i][j][r] = 0.f;

    uint32_t a_off = (uint32_t)((wm*32 + (lane & 15)) * 80 + (lane >> 4) * 16);
    uint32_t b_off = (uint32_t)((wn*64 + (lane & 7) + ((lane >> 4) << 3)) * 80
                                + ((lane >> 3) & 1) * 16);
    uint32_t smem_base = smem_u32(smem);

    int nch = K >> 5;
    prefetch_tile(smem, 0, A, lda, B, ldb, m0, n0, 0, tid);
    CP_COMMIT();
    prefetch_tile(smem, 1, A, lda, B, ldb, m0, n0, 32, tid);
    CP_COMMIT();

    int st = 0;
    for (int c = 0; c < nch; c++) {
        if (c + 2 <= nch) CP_WAIT1(); else CP_WAIT0();
        __syncthreads();
        if (c + 2 < nch) {
            int nst = st + 2; if (nst >= 3) nst -= 3;
            prefetch_tile(smem, nst, A, lda, B, ldb, m0, n0, (c+2)*32, tid);
            CP_COMMIT();
        }

        uint32_t as_b = smem_base + st*STAGE_BYTES + a_off;
        uint32_t bs_b = smem_base + st*STAGE_BYTES + 5120 + b_off;
#pragma unroll
        for (int ks = 0; ks < 2; ks++) {
            uint32_t a[2][4], b[4][4];
#pragma unroll
            for (int mf = 0; mf < 2; mf++)
                LDM_X4(a[mf][0], a[mf][1], a[mf][2], a[mf][3], as_b + mf*1280 + ks*32);
#pragma unroll
            for (int nf2 = 0; nf2 < 4; nf2++)
                LDM_X4(b[nf2][0], b[nf2][1], b[nf2][2], b[nf2][3], bs_b + nf2*1280 + ks*32);
#pragma unroll
            for (int mf = 0; mf < 2; mf++)
#pragma unroll
                for (int nf = 0; nf < 8; nf++)
                    MMA16816(acc[mf][nf], a[mf], b[nf>>1][(nf&1)*2], b[nf>>1][(nf&1)*2+1]);
        }
        st++; if (st == 3) st = 0;
    }

    int r4 = lane >> 2, cp = (lane & 3) * 2;

    if constexpr (EPI == 0) {
        if (n0 < 1024) {             // Q / K direct half2 stores
            f16* dst = (n0 < 512) ? g_q2 : g_k2;
            int nbase = (n0 < 512) ? n0 : (n0 - 512);
#pragma unroll
            for (int mf = 0; mf < 2; mf++)
#pragma unroll
                for (int nf = 0; nf < 8; nf++) {
                    int rr = m0 + wm*32 + mf*16 + r4;
                    int cc = wn*64 + nf*8 + cp;
                    float b0 = bias[n0 + cc], b1 = bias[n0 + cc + 1];
                    *(__half2*)&dst[(size_t)rr * 512 + nbase + cc] =
                        __floats2half2_rn(acc[mf][nf][0] + b0, acc[mf][nf][1] + b1);
                    *(__half2*)&dst[(size_t)(rr + 8) * 512 + nbase + cc] =
                        __floats2half2_rn(acc[mf][nf][2] + b0, acc[mf][nf][3] + b1);
                }
        } else {                     // V: staged transpose -> [B,C,S]
            __syncthreads();
            float* tile = (float*)smem;
#pragma unroll
            for (int mf = 0; mf < 2; mf++)
#pragma unroll
                for (int nf = 0; nf < 8; nf++) {
                    int rr = wm*32 + mf*16 + r4, cc = wn*64 + nf*8 + cp;
                    tile[rr*132 + cc]       = acc[mf][nf][0];
                    tile[rr*132 + cc + 1]   = acc[mf][nf][1];
                    tile[(rr+8)*132 + cc]   = acc[mf][nf][2];
                    tile[(rr+8)*132 + cc+1] = acc[mf][nf][3];
                }
            __syncthreads();
            for (int idx = tid; idx < 8192; idx += 128) {
                int rt = idx & 63, ct = idx >> 6;
                float v = tile[rt*132 + ct] + bias[n0 + ct];
                int m = m0 + rt, b = m >> 10, s = m & 1023;
                int cg = n0 + ct - 1024;
                g_v2[((size_t)b*512 + cg) * 1024 + s] = __float2half_rn(v);
            }
        }
    } else if constexpr (EPI == 1) { // scores fp32 direct float2
        float* op = Out + (size_t)z * SS * SS;
#pragma unroll
        for (int mf = 0; mf < 2; mf++)
#pragma unroll
            for (int nf = 0; nf < 8; nf++) {
                int rr = m0 + wm*32 + mf*16 + r4;
                int cc = n0 + wn*64 + nf*8 + cp;
                float2 v0 = {acc[mf][nf][0] * scale, acc[mf][nf][1] * scale};
                float2 v1 = {acc[mf][nf][2] * scale, acc[mf][nf][3] * scale};
                *(float2*)&op[(size_t)rr * SS + cc] = v0;
                *(float2*)&op[(size_t)(rr + 8) * SS + cc] = v1;
            }
    } else if constexpr (EPI == 2) { // AV direct half2
#pragma unroll
        for (int mf = 0; mf < 2; mf++)
#pragma unroll
            for (int nf = 0; nf < 8; nf++) {
                int rr = m0 + wm*32 + mf*16 + r4;
                int cc = n0 + wn*64 + nf*8 + cp;
                *(__half2*)&g_ao2[((size_t)z * SS + rr) * 512 + cc] =
                    __floats2half2_rn(acc[mf][nf][0], acc[mf][nf][1]);
                *(__half2*)&g_ao2[((size_t)z * SS + rr + 8) * 512 + cc] =
                    __floats2half2_rn(acc[mf][nf][2], acc[mf][nf][3]);
            }
    } else {                         // proj^T: m=c-dim, n=global s; direct float2 + bias + resid
#pragma unroll
        for (int mf = 0; mf < 2; mf++) {
            int rr = m0 + wm*32 + mf*16 + r4;
            float bias_r  = bias[rr], bias_r8 = bias[rr + 8];
#pragma unroll
            for (int nf = 0; nf < 8; nf++) {
                int n = n0 + wn*64 + nf*8 + cp;
                int b = n >> 10, s = n & 1023;
                size_t o0 = ((size_t)b * 512 + rr) * 1024 + s;
                size_t o1 = ((size_t)b * 512 + rr + 8) * 1024 + s;
                float2 rv0 = *(const float2*)&resid[o0];
                float2 rv1 = *(const float2*)&resid[o1];
                float2 w0 = {acc[mf][nf][0] + bias_r  + rv0.x, acc[mf][nf][1] + bias_r  + rv0.y};
                float2 w1 = {acc[mf][nf][2] + bias_r8 + rv1.x, acc[mf][nf][3] + bias_r8 + rv1.y};
                *(float2*)&Out[o0] = w0;
                *(float2*)&Out[o1] = w1;
            }
        }
    }
}

// ---------------- softmax over 1024-wide rows, plain fp16 output ----------------
__global__ void softmax_rows(const float* __restrict__ sc) {
    const float* row = sc + (size_t)blockIdx.x * SS;
    f16* orow = g_p2 + (size_t)blockIdx.x * 1024;
    int t = threadIdx.x;
    float v[4];
#pragma unroll
    for (int i = 0; i < 4; i++) v[i] = row[t + i*256];
    float m = fmaxf(fmaxf(v[0], v[1]), fmaxf(v[2], v[3]));
    __shared__ float red[8];
    for (int o = 16; o > 0; o >>= 1) m = fmaxf(m, __shfl_xor_sync(0xffffffffu, m, o));
    if ((t & 31) == 0) red[t >> 5] = m;
    __syncthreads();
    float mm = fmaxf(fmaxf(fmaxf(red[0], red[1]), fmaxf(red[2], red[3])),
                     fmaxf(fmaxf(red[4], red[5]), fmaxf(red[6], red[7])));
    float s = 0.f;
#pragma unroll
    for (int i = 0; i < 4; i++) { v[i] = __expf(v[i] - mm); s += v[i]; }
    for (int o = 16; o > 0; o >>= 1) s += __shfl_xor_sync(0xffffffffu, s, o);
    __syncthreads();
    if ((t & 31) == 0) red[t >> 5] = s;
    __syncthreads();
    float tot = ((red[0]+red[1]) + (red[2]+red[3])) + ((red[4]+red[5]) + (red[6]+red[7]));
    float invs = 1.f / tot;
#pragma unroll
    for (int i = 0; i < 4; i++)
        orow[t + i*256] = __float2half_rn(v[i] * invs);
}

// ---------------- launch ----------------
extern "C" void kernel_launch(void* const* d_in, const int* in_sizes, int n_in,
                              void* d_out, int out_size) {
    const float* x      = (const float*)d_in[0];
    const float* gn_w   = (const float*)d_in[1];
    const float* gn_b   = (const float*)d_in[2];
    const float* qkv_w  = (const float*)d_in[3];
    const float* qkv_b  = (const float*)d_in[4];
    const float* proj_w = (const float*)d_in[5];
    const float* proj_b = (const float*)d_in[6];
    float* out = (float*)d_out;

    cudaFuncSetAttribute(mm_gemm<0>, cudaFuncAttributeMaxDynamicSharedMemorySize, DYN_SMEM);
    cudaFuncSetAttribute(mm_gemm<1>, cudaFuncAttributeMaxDynamicSharedMemorySize, DYN_SMEM);
    cudaFuncSetAttribute(mm_gemm<2>, cudaFuncAttributeMaxDynamicSharedMemorySize, DYN_SMEM);
    cudaFuncSetAttribute(mm_gemm<3>, cudaFuncAttributeMaxDynamicSharedMemorySize, DYN_SMEM);

    f16 *h2, *w1, *w2, *q2, *k2, *v2, *p2, *ao2; float* sc;
    cudaGetSymbolAddress((void**)&h2,  g_h2);
    cudaGetSymbolAddress((void**)&w1,  g_w1);
    cudaGetSymbolAddress((void**)&w2,  g_w2);
    cudaGetSymbolAddress((void**)&q2,  g_q2);
    cudaGetSymbolAddress((void**)&k2,  g_k2);
    cudaGetSymbolAddress((void**)&v2,  g_v2);
    cudaGetSymbolAddress((void**)&p2,  g_p2);
    cudaGetSymbolAddress((void**)&ao2, g_ao2);
    cudaGetSymbolAddress((void**)&sc,  g_sc);

    // 1. weight convert
    wconv<<<(2048*512 + 255)/256, 256>>>(qkv_w, proj_w);

    // 2. fused GroupNorm stats
    gn_stats<<<dim3(64, BB), 256>>>(x);

    // 3. normalize + transpose (fp16)
    norm_split<<<dim3(SS/32, CC/32, BB), dim3(32, 8)>>>(x, gn_w, gn_b);

    // 4. QKV GEMM: M=16384, N=1536, K=512
    mm_gemm<0><<<dim3(12, 256, 1), 128, DYN_SMEM>>>(
        h2, 512, 0LL, w1, 512, 0LL,
        nullptr, qkv_b, nullptr, 1.f, 512);

    // 5. scores = scale * Q K^T, batched: K=512
    mm_gemm<1><<<dim3(8, 16, BB), 128, DYN_SMEM>>>(
        q2, 512, 1024LL*512, k2, 512, 1024LL*512, sc,
        nullptr, nullptr, 0.044194173824159216f, 512);

    // 6. softmax
    softmax_rows<<<BB*SS, 256>>>(sc);

    // 7. attn @ V: M=1024, N=512, K=1024, batched
    mm_gemm<2><<<dim3(4, 16, BB), 128, DYN_SMEM>>>(
        p2, 1024, 1024LL*1024, v2, 1024, 512LL*1024, nullptr,
        nullptr, nullptr, 1.f, 1024);

    // 8. proj^T + bias + residual -> NCHW out: M=512 (c), N=16384 (b*s), K=512
    mm_gemm<3><<<dim3(128, 8, 1), 128, DYN_SMEM>>>(
        w2, 512, 0LL, ao2, 512, 0LL, out, proj_b, x, 1.f, 512);
}